// round 8
// baseline (speedup 1.0000x reference)
#include <cuda_runtime.h>

// Problem dims (fixed by the dataset; runtime values derived from in_sizes).
#define NMAX 50000
#define EMAX 800000

// ---- scratch (device globals; no allocation allowed) ----
__device__ float g_q[NMAX * 128];
__device__ float g_k[NMAX * 128];
__device__ float g_v[NMAX * 128];
__device__ float g_G[NMAX * 64];    // G[n,h*16+i] = sum_d We[i,h*32+d] * q[n,h*32+d]
__device__ float g_h1[NMAX * 32];   // layer-1 output (skip + attention)
__device__ float g_h2[NMAX * 32];   // layer-2 output
__device__ float g_us[NMAX * 32];   // relu(h2) @ Wm1[0:32]
__device__ float g_ud[NMAX * 32];   // relu(h2) @ Wm1[48:80]
__device__ float g_expa[EMAX * 4];  // exp(alpha) per SORTED edge position, 4 heads

// ---- CSR (dst-sorted edges), built once per launch ----
__device__ int g_deg[NMAX];
__device__ int g_rowptr[NMAX + 1];
__device__ int g_cursor[NMAX];
__device__ int g_srcsorted[EMAX];
__device__ int g_dstsorted[EMAX];
__device__ int g_eidsorted[EMAX];
__device__ int g_blocksums[256];    // (NMAX+255)/256 = 196 <= 256

// ===========================================================================
// CSR build: zero -> histogram -> 3-phase scan -> scatter
// ===========================================================================
__global__ void csr_zero_kernel(int N) {
    int i = blockIdx.x * blockDim.x + threadIdx.x;
    if (i < N) g_deg[i] = 0;
}

__global__ void csr_hist_kernel(const int* __restrict__ ei, int E) {
    int e = blockIdx.x * blockDim.x + threadIdx.x;
    if (e < E) atomicAdd(&g_deg[ei[E + e]], 1);
}

__global__ void csr_scan1_kernel(int N) {
    __shared__ int sh[256];
    int tid = threadIdx.x;
    int i = blockIdx.x * 256 + tid;
    int v = (i < N) ? g_deg[i] : 0;
    sh[tid] = v;
    __syncthreads();
#pragma unroll
    for (int off = 1; off < 256; off <<= 1) {
        int t = (tid >= off) ? sh[tid - off] : 0;
        __syncthreads();
        sh[tid] += t;
        __syncthreads();
    }
    if (i < N) g_rowptr[i + 1] = sh[tid];   // local inclusive, fixed in scan3
    if (tid == 255) g_blocksums[blockIdx.x] = sh[255];
}

__global__ void csr_scan2_kernel(int nb) {
    __shared__ int sh[256];
    int tid = threadIdx.x;
    int orig = (tid < nb) ? g_blocksums[tid] : 0;
    sh[tid] = orig;
    __syncthreads();
#pragma unroll
    for (int off = 1; off < 256; off <<= 1) {
        int t = (tid >= off) ? sh[tid - off] : 0;
        __syncthreads();
        sh[tid] += t;
        __syncthreads();
    }
    if (tid < nb) g_blocksums[tid] = sh[tid] - orig;  // exclusive
}

__global__ void csr_scan3_kernel(int N) {
    int i = blockIdx.x * blockDim.x + threadIdx.x;
    if (i < N) {
        int off = g_blocksums[i >> 8];
        int incl = g_rowptr[i + 1] + off;
        g_rowptr[i + 1] = incl;
        g_cursor[i] = incl - g_deg[i];
    }
    if (i == 0) g_rowptr[0] = 0;
}

__global__ void csr_scatter_kernel(const int* __restrict__ ei, int E) {
    int e = blockIdx.x * blockDim.x + threadIdx.x;
    if (e >= E) return;
    int src = ei[e];
    int dst = ei[E + e];
    int p = atomicAdd(&g_cursor[dst], 1);
    g_srcsorted[p] = src;
    g_dstsorted[p] = dst;
    g_eidsorted[p] = e;
}

// ===========================================================================
// Node linears: q/k/v = x@W+b ([N,128]); skip = x@Ws+bs ([N,32]) into outbuf;
// G[n, w*16+i] = sum_d We[i, w*32+d] * q[n, w*32+d]  (warp w = head).
// One block per node, 128 threads.
// ===========================================================================
__global__ void node_linear_kernel(
    const float* __restrict__ xin, int layer,
    const float* __restrict__ Wq, const float* __restrict__ bq,
    const float* __restrict__ Wk, const float* __restrict__ bk,
    const float* __restrict__ Wv, const float* __restrict__ bv,
    const float* __restrict__ Ws, const float* __restrict__ bs,
    const float* __restrict__ We,
    int N)
{
    int n = blockIdx.x;
    if (n >= N) return;
    int j = threadIdx.x;  // 0..127
    int w = j >> 5;       // head
    int lane = j & 31;

    __shared__ float xs[32];
    if (j < 32) {
        float t = layer ? fmaxf(g_h1[n * 32 + j], 0.0f) : xin[n * 32 + j];
        xs[j] = t;
    }
    __syncthreads();

    float aq = bq[j], ak = bk[j], av = bv[j];
#pragma unroll
    for (int i = 0; i < 32; i++) {
        float xi = xs[i];
        aq = fmaf(xi, Wq[i * 128 + j], aq);
        ak = fmaf(xi, Wk[i * 128 + j], ak);
        av = fmaf(xi, Wv[i * 128 + j], av);
    }
    g_q[n * 128 + j] = aq;
    g_k[n * 128 + j] = ak;
    g_v[n * 128 + j] = av;

#pragma unroll
    for (int i = 0; i < 16; i++) {
        float t = We[i * 128 + j] * aq;
#pragma unroll
        for (int off = 16; off > 0; off >>= 1)
            t += __shfl_xor_sync(0xffffffffu, t, off);
        if (lane == 0) g_G[n * 64 + w * 16 + i] = t;
    }

    if (j < 32) {
        float as = bs[j];
#pragma unroll
        for (int i = 0; i < 32; i++) as = fmaf(xs[i], Ws[i * 32 + j], as);
        float* outbuf = layer ? g_h2 : g_h1;
        outbuf[n * 32 + j] = as;
    }
}

// ===========================================================================
// Edge alpha (sorted order): one warp per sorted edge position p.
//   alpha_h = q[dst].k[src]|_h + sum_i ea_i * G[dst][h,i]
//   expa[p*4+h] = exp(alpha_h / sqrt(32))
// Massively parallel -> shuffle-chain latency fully hidden. No atomics.
// Reduce: 3 butterfly steps on 4 regs (bits 4,3,2), per-octet head pick,
// 2 more steps (bits 0,1) -> 14 shuffles.
// ===========================================================================
__global__ void edge_alpha_kernel(const float* __restrict__ ea, int E)
{
    int p = (int)((blockIdx.x * blockDim.x + threadIdx.x) >> 5);
    int lane = threadIdx.x & 31;
    if (p >= E) return;

    int src = g_srcsorted[p];
    int dst = g_dstsorted[p];
    int eid = g_eidsorted[p];

    float eav = (lane < 16) ? ea[(size_t)eid * 16 + lane] : 0.0f;

    const float* qrow = &g_q[dst * 128];
    const float* krow = &g_k[src * 128];
    float a0 = qrow[lane]      * krow[lane];
    float a1 = qrow[32 + lane] * krow[32 + lane];
    float a2 = qrow[64 + lane] * krow[64 + lane];
    float a3 = qrow[96 + lane] * krow[96 + lane];
    if (lane < 16) {
        const float* Grow = &g_G[dst * 64];
        a0 = fmaf(eav, Grow[lane],      a0);
        a1 = fmaf(eav, Grow[16 + lane], a1);
        a2 = fmaf(eav, Grow[32 + lane], a2);
        a3 = fmaf(eav, Grow[48 + lane], a3);
    }
    // reduce bits 4,3,2 on all four regs
#pragma unroll
    for (int off = 16; off >= 4; off >>= 1) {
        a0 += __shfl_xor_sync(0xffffffffu, a0, off);
        a1 += __shfl_xor_sync(0xffffffffu, a1, off);
        a2 += __shfl_xor_sync(0xffffffffu, a2, off);
        a3 += __shfl_xor_sync(0xffffffffu, a3, off);
    }
    // octet o = lane>>3 takes head o; finish residues (bits 0,1)
    int o = lane >> 3;
    float r = a0;
    if (o == 1) r = a1;
    else if (o == 2) r = a2;
    else if (o == 3) r = a3;
    r += __shfl_xor_sync(0xffffffffu, r, 1);
    r += __shfl_xor_sync(0xffffffffu, r, 2);

    float av = __expf(r * 0.17677669529663687f);  // 1/sqrt(32)
    if ((lane & 7) == 0)
        g_expa[(size_t)p * 4 + o] = av;
}

// ===========================================================================
// Per-node aggregation: one warp per node, CSR loop, NO reductions in loop.
// Per edge: uniform float4 load of expa (sequential), 4 v-gathers, ea load,
// 1 shuffle. Accumulators are independent fp chains -> deep pipelining.
// ===========================================================================
__global__ void node_aggr_kernel(const float* __restrict__ ea,
                                 const float* __restrict__ We,
                                 int layer, int N)
{
    __shared__ float sWe[2048];  // 16 x 128
    for (int t = threadIdx.x; t < 2048; t += blockDim.x) sWe[t] = We[t];
    __syncthreads();

    int n = (int)((blockIdx.x * blockDim.x + threadIdx.x) >> 5);
    int lane = threadIdx.x & 31;
    if (n >= N) return;

    int rs = g_rowptr[n];
    int re = g_rowptr[n + 1];

    float accO0 = 0.0f, accO1 = 0.0f, accO2 = 0.0f, accO3 = 0.0f;
    float accT0 = 0.0f, accT1 = 0.0f;  // T[hb,i], T[2+hb,i]; hb=lane>>4, i=lane&15
    float s0 = 0.0f, s1 = 0.0f, s2 = 0.0f, s3 = 0.0f;  // redundant across lanes
    int hb = lane >> 4;

#pragma unroll 2
    for (int p = rs; p < re; p++) {
        int src = g_srcsorted[p];
        int eid = g_eidsorted[p];

        float4 ev = *reinterpret_cast<const float4*>(&g_expa[(size_t)p * 4]);  // uniform

        float eav = (lane < 16) ? ea[(size_t)eid * 16 + lane] : 0.0f;

        const float* vrow = &g_v[src * 128];
        accO0 = fmaf(ev.x, vrow[lane],      accO0);
        accO1 = fmaf(ev.y, vrow[32 + lane], accO1);
        accO2 = fmaf(ev.z, vrow[64 + lane], accO2);
        accO3 = fmaf(ev.w, vrow[96 + lane], accO3);

        float eai = __shfl_sync(0xffffffffu, eav, lane & 15);  // lower half value
        accT0 = fmaf((hb == 0) ? ev.x : ev.y, eai, accT0);
        accT1 = fmaf((hb == 0) ? ev.z : ev.w, eai, accT1);

        s0 += ev.x; s1 += ev.y; s2 += ev.z; s3 += ev.w;
    }

    float inv0 = 1.0f / (s0 + 1e-16f);
    float inv1 = 1.0f / (s1 + 1e-16f);
    float inv2 = 1.0f / (s2 + 1e-16f);
    float inv3 = 1.0f / (s3 + 1e-16f);

    // v-part
    float res = inv0 * accO0;
    res = fmaf(inv1, accO1, res);
    res = fmaf(inv2, accO2, res);
    res = fmaf(inv3, accO3, res);

    // e-part: sum_h inv_h * sum_i We[i, h*32+lane] * T[h,i]
#pragma unroll
    for (int h = 0; h < 4; h++) {
        float acc = 0.0f;
#pragma unroll
        for (int i = 0; i < 16; i++) {
            float t = (h < 2) ? __shfl_sync(0xffffffffu, accT0, h * 16 + i)
                              : __shfl_sync(0xffffffffu, accT1, (h - 2) * 16 + i);
            acc = fmaf(sWe[i * 128 + h * 32 + lane], t, acc);
        }
        float inv = (h == 0) ? inv0 : (h == 1) ? inv1 : (h == 2) ? inv2 : inv3;
        res = fmaf(inv, acc, res);
    }

    float* outbuf = layer ? g_h2 : g_h1;
    outbuf[n * 32 + lane] += 0.25f * res;   // skip already there; no atomics
}

// ===========================================================================
// MLP node precompute: u_src = relu(h2)@Wm1[0:32], u_dst = relu(h2)@Wm1[48:80]
// ===========================================================================
__global__ void mlp_pre_kernel(const float* __restrict__ Wm1, int N)
{
    __shared__ float sWa[1024];
    __shared__ float sWc[1024];
    for (int t = threadIdx.x; t < 1024; t += blockDim.x) {
        sWa[t] = Wm1[t];
        sWc[t] = Wm1[1536 + t];
    }
    __syncthreads();

    int n = (int)((blockIdx.x * blockDim.x + threadIdx.x) >> 5);
    int lane = threadIdx.x & 31;
    if (n >= N) return;

    float r = fmaxf(g_h2[n * 32 + lane], 0.0f);
    float us = 0.0f, ud = 0.0f;
#pragma unroll
    for (int i = 0; i < 32; i++) {
        float xi = __shfl_sync(0xffffffffu, r, i);
        us = fmaf(xi, sWa[i * 32 + lane], us);
        ud = fmaf(xi, sWc[i * 32 + lane], ud);
    }
    g_us[n * 32 + lane] = us;
    g_ud[n * 32 + lane] = ud;
}

// ===========================================================================
// Edge MLP: one warp per edge.
// ===========================================================================
__global__ void edge_mlp_kernel(
    const int* __restrict__ ei, const float* __restrict__ ea,
    const float* __restrict__ Wm1, const float* __restrict__ bm1,
    const float* __restrict__ Wm2, const float* __restrict__ bm2,
    float* __restrict__ out, int E)
{
    __shared__ float sWe2[512];
    __shared__ float sb1[32];
    __shared__ float sW2[32];
    for (int t = threadIdx.x; t < 512; t += blockDim.x) sWe2[t] = Wm1[1024 + t];
    if (threadIdx.x < 32) {
        sb1[threadIdx.x] = bm1[threadIdx.x];
        sW2[threadIdx.x] = Wm2[threadIdx.x];
    }
    __syncthreads();

    int e = (int)((blockIdx.x * blockDim.x + threadIdx.x) >> 5);
    int lane = threadIdx.x & 31;
    if (e >= E) return;

    int src = ei[e];
    int dst = ei[E + e];

    float eav = (lane < 16) ? ea[(size_t)e * 16 + lane] : 0.0f;

    float t = g_us[src * 32 + lane] + g_ud[dst * 32 + lane] + sb1[lane];
#pragma unroll
    for (int i = 0; i < 16; i++) {
        float xi = __shfl_sync(0xffffffffu, eav, i);
        t = fmaf(xi, sWe2[i * 32 + lane], t);
    }
    float o = fmaxf(t, 0.0f) * sW2[lane];
#pragma unroll
    for (int off = 16; off > 0; off >>= 1)
        o += __shfl_xor_sync(0xffffffffu, o, off);
    if (lane == 0) out[e] = o + bm2[0];
}

// ===========================================================================
extern "C" void kernel_launch(void* const* d_in, const int* in_sizes, int n_in,
                              void* d_out, int out_size)
{
    const float* x  = (const float*)d_in[0];
    const float* ea = (const float*)d_in[1];
    const int*   ei = (const int*)d_in[2];

    const float* Wq1 = (const float*)d_in[3];
    const float* bq1 = (const float*)d_in[4];
    const float* Wk1 = (const float*)d_in[5];
    const float* bk1 = (const float*)d_in[6];
    const float* Wv1 = (const float*)d_in[7];
    const float* bv1 = (const float*)d_in[8];
    const float* We1 = (const float*)d_in[9];
    const float* Ws1 = (const float*)d_in[10];
    const float* bs1 = (const float*)d_in[11];

    const float* Wq2 = (const float*)d_in[12];
    const float* bq2 = (const float*)d_in[13];
    const float* Wk2 = (const float*)d_in[14];
    const float* bk2 = (const float*)d_in[15];
    const float* Wv2 = (const float*)d_in[16];
    const float* bv2 = (const float*)d_in[17];
    const float* We2 = (const float*)d_in[18];
    const float* Ws2 = (const float*)d_in[19];
    const float* bs2 = (const float*)d_in[20];

    const float* Wm1 = (const float*)d_in[21];
    const float* bm1 = (const float*)d_in[22];
    const float* Wm2 = (const float*)d_in[23];
    const float* bm2 = (const float*)d_in[24];

    float* out = (float*)d_out;

    int N = in_sizes[0] / 32;
    int E = in_sizes[1] / 16;

    int nBlocks256  = (N + 255) / 256;
    int eBlocks256  = (E + 255) / 256;
    int edgeWarpBlocks = (E + 7) / 8;
    int nodeWarpBlocks = (N + 7) / 8;
    int nbScan = (N + 255) / 256;

    // ---- CSR build (shared by both layers) ----
    csr_zero_kernel<<<nBlocks256, 256>>>(N);
    csr_hist_kernel<<<eBlocks256, 256>>>(ei, E);
    csr_scan1_kernel<<<nbScan, 256>>>(N);
    csr_scan2_kernel<<<1, 256>>>(nbScan);
    csr_scan3_kernel<<<nBlocks256, 256>>>(N);
    csr_scatter_kernel<<<eBlocks256, 256>>>(ei, E);

    // ---- Layer 1 ----
    node_linear_kernel<<<N, 128>>>(x, 0, Wq1, bq1, Wk1, bk1, Wv1, bv1, Ws1, bs1, We1, N);
    edge_alpha_kernel<<<edgeWarpBlocks, 256>>>(ea, E);
    node_aggr_kernel<<<nodeWarpBlocks, 256>>>(ea, We1, 0, N);

    // ---- Layer 2 ----
    node_linear_kernel<<<N, 128>>>(nullptr, 1, Wq2, bq2, Wk2, bk2, Wv2, bv2, Ws2, bs2, We2, N);
    edge_alpha_kernel<<<edgeWarpBlocks, 256>>>(ea, E);
    node_aggr_kernel<<<nodeWarpBlocks, 256>>>(ea, We2, 1, N);

    // ---- Edge MLP ----
    mlp_pre_kernel<<<nodeWarpBlocks, 256>>>(Wm1, N);
    edge_mlp_kernel<<<edgeWarpBlocks, 256>>>(ei, ea, Wm1, bm1, Wm2, bm2, out, E);
}